// round 1
// baseline (speedup 1.0000x reference)
#include <cuda_runtime.h>

// Problem shapes (fixed by the dataset)
#define BB   16
#define NN   2048
#define FIN  128
#define FO   64
#define TI   128       // i-rows per block (one per thread)
#define TJ   64        // j-tile
#define ALPHA 0.2f

// Scratch (allocation-free rule: __device__ globals)
__device__ float g_Wh[BB * NN * FO];   // 8 MB
__device__ float g_fi[BB * NN];
__device__ float g_fj[BB * NN];

// ---- packed f32x2 helpers (sm_103a FFMA2: 2x fp32 FMA throughput) ----
__device__ __forceinline__ void fma2(unsigned long long& d,
                                     unsigned long long a,
                                     unsigned long long b) {
    asm("fma.rn.f32x2 %0, %1, %2, %0;" : "+l"(d) : "l"(a), "l"(b));
}
__device__ __forceinline__ unsigned long long pack2(float x, float y) {
    unsigned long long r;
    asm("mov.b64 %0, {%1, %2};" : "=l"(r) : "f"(x), "f"(y));
    return r;
}
__device__ __forceinline__ float2 unpack2(unsigned long long v) {
    float2 r;
    asm("mov.b64 {%0, %1}, %2;" : "=f"(r.x), "=f"(r.y) : "l"(v));
    return r;
}

// ============================================================
// Kernel 1: Wh = h @ W  (and f_i = Wh@a_src, f_j = Wh@a_dst)
// block = 256 threads, 16 rows; thread -> (row r = tid>>4, o-quad og = tid&15)
// ============================================================
__global__ __launch_bounds__(256)
void gat_wh_kernel(const float* __restrict__ h,
                   const float* __restrict__ W,
                   const float* __restrict__ a) {
    __shared__ float h_s[16 * FIN];    // 8 KB
    __shared__ float W_s[FIN * FO];    // 32 KB

    int tid = threadIdx.x;
    size_t base = (size_t)blockIdx.x * 16;   // global row base (flat B*N rows)

    // cooperative loads (coalesced float4)
    {
        const float4* hsrc = (const float4*)(h + base * FIN);
        float4* hdst = (float4*)h_s;
        #pragma unroll
        for (int r = 0; r < 2; r++) hdst[r * 256 + tid] = hsrc[r * 256 + tid];
        const float4* wsrc = (const float4*)W;
        float4* wdst = (float4*)W_s;
        #pragma unroll
        for (int r = 0; r < 8; r++) wdst[r * 256 + tid] = wsrc[r * 256 + tid];
    }
    __syncthreads();

    int r  = tid >> 4;
    int og = tid & 15;

    unsigned long long acc0 = 0ull, acc1 = 0ull;
    const float* hrow = h_s + r * FIN;
    #pragma unroll 8
    for (int k = 0; k < FIN; k++) {
        float hv = hrow[k];                       // broadcast LDS
        unsigned long long hv2 = pack2(hv, hv);
        const ulonglong2* wp = (const ulonglong2*)(W_s + k * FO + og * 4);
        ulonglong2 w = *wp;                       // LDS.128
        fma2(acc0, hv2, w.x);
        fma2(acc1, hv2, w.y);
    }
    float2 a01 = unpack2(acc0), a23 = unpack2(acc1);

    size_t row = base + r;
    float4 v = make_float4(a01.x, a01.y, a23.x, a23.y);
    ((float4*)(g_Wh + row * FO))[og] = v;

    // f_i / f_j: dot with a_src (a[0:64]) and a_dst (a[64:128]); reduce over 16 lanes
    int o = og * 4;
    float ps = a01.x * a[o]      + a01.y * a[o + 1]      + a23.x * a[o + 2]      + a23.y * a[o + 3];
    float pd = a01.x * a[FO + o] + a01.y * a[FO + o + 1] + a23.x * a[FO + o + 2] + a23.y * a[FO + o + 3];
    #pragma unroll
    for (int off = 8; off >= 1; off >>= 1) {
        ps += __shfl_down_sync(0xffffffffu, ps, off, 16);
        pd += __shfl_down_sync(0xffffffffu, pd, off, 16);
    }
    if (og == 0) { g_fi[row] = ps; g_fj[row] = pd; }
}

// ============================================================
// Kernel 2: fused masked-softmax attention + P@Wh + relu
// grid = (N/TI, B), block = TI threads, one output row per thread.
// No max-shift needed: logits bounded (|f|~O(5)), exp never overflows,
// masked entries contribute exactly 0 -> identical to reference softmax.
// ============================================================
__global__ __launch_bounds__(TI, 4)
void gat_attn_kernel(const float* __restrict__ adj,
                     const float* __restrict__ mask,
                     float* __restrict__ out) {
    __shared__ float Wh_s[TJ * FO];   // 16 KB
    __shared__ float p_s[TI * TJ];    // 32 KB (XOR-swizzled)

    int tid = threadIdx.x;
    int b   = blockIdx.y;
    int i0  = blockIdx.x * TI;

    const float* adj_b  = adj  + (size_t)b * NN * NN;
    const float* mask_b = mask + (size_t)b * NN;
    const float* Wh_b   = g_Wh + (size_t)b * NN * FO;
    const float* fi_b   = g_fi + (size_t)b * NN;
    const float* fj_b   = g_fj + (size_t)b * NN;

    unsigned long long acc[32];
    #pragma unroll
    for (int q = 0; q < 32; q++) acc[q] = 0ull;
    float rowsum = 0.f;

    int jfix   = tid & 63;   // this thread's fixed j-column in the p-stage
    int ishift = tid >> 6;   // 0 or 1

    for (int j0 = 0; j0 < NN; j0 += TJ) {
        __syncthreads();

        // -- stage Wh tile (coalesced) --
        {
            const float4* src = (const float4*)(Wh_b + (size_t)j0 * FO);
            float4* dst = (float4*)Wh_s;
            #pragma unroll
            for (int r2 = 0; r2 < 8; r2++) dst[r2 * TI + tid] = src[r2 * TI + tid];
        }

        // -- compute p tile: p = active ? exp(leakyrelu(fi+fj)) : 0 --
        float fjv = fj_b[j0 + jfix];
        float mj  = mask_b[j0 + jfix];
        bool  jok = (mj > 0.f);
        const float* adj_col = adj_b + (size_t)i0 * NN + j0 + jfix;
        #pragma unroll 4
        for (int rep = 0; rep < 64; rep++) {
            int il = 2 * rep + ishift;
            float av  = adj_col[(size_t)il * NN];      // coalesced along j
            float fiv = fi_b[i0 + il];                 // L1 broadcast
            float miv = mask_b[i0 + il];
            float x  = fiv + fjv;
            float l  = fmaxf(x, ALPHA * x);            // leaky_relu
            float pe = __expf(l);
            float p  = (av > 0.f && jok && miv > 0.f) ? pe : 0.f;
            p_s[il * TJ + (jfix ^ (il & 31))] = p;     // swizzled store
        }
        __syncthreads();

        // -- accumulate: acc[o] += p_ij * Wh[j][o], rowsum += p_ij --
        int sw = tid & 31;
        const float* prow = p_s + tid * TJ;
        #pragma unroll 4
        for (int j = 0; j < TJ; j++) {
            float p = prow[j ^ sw];                    // conflict-free via swizzle
            rowsum += p;
            unsigned long long p2 = pack2(p, p);
            const ulonglong2* wp = (const ulonglong2*)(Wh_s + j * FO);
            #pragma unroll
            for (int f = 0; f < 16; f++) {
                ulonglong2 w = wp[f];                  // LDS.128, broadcast
                fma2(acc[2 * f],     p2, w.x);
                fma2(acc[2 * f + 1], p2, w.y);
            }
        }
    }

    // epilogue: normalize + relu
    float inv = (rowsum > 0.f) ? (1.f / rowsum) : 0.f;
    float* op = out + ((size_t)b * NN + i0 + tid) * FO;
    #pragma unroll
    for (int f = 0; f < 16; f++) {
        float2 v0 = unpack2(acc[2 * f]);
        float2 v1 = unpack2(acc[2 * f + 1]);
        float4 v;
        v.x = fmaxf(v0.x * inv, 0.f);
        v.y = fmaxf(v0.y * inv, 0.f);
        v.z = fmaxf(v1.x * inv, 0.f);
        v.w = fmaxf(v1.y * inv, 0.f);
        ((float4*)op)[f] = v;
    }
}

// ============================================================
extern "C" void kernel_launch(void* const* d_in, const int* in_sizes, int n_in,
                              void* d_out, int out_size) {
    // Identify inputs by element count (all counts are distinct) — robust to ordering.
    const float *h = nullptr, *adj = nullptr, *mask = nullptr, *W = nullptr, *a = nullptr;
    for (int i = 0; i < n_in; i++) {
        switch (in_sizes[i]) {
            case BB * NN * FIN:  h    = (const float*)d_in[i]; break;  // 4194304
            case BB * NN * NN:   adj  = (const float*)d_in[i]; break;  // 67108864
            case BB * NN:        mask = (const float*)d_in[i]; break;  // 32768
            case FIN * FO:       W    = (const float*)d_in[i]; break;  // 8192
            case 2 * FO:         a    = (const float*)d_in[i]; break;  // 128
        }
    }
    float* out = (float*)d_out;

    gat_wh_kernel<<<BB * NN / 16, 256>>>(h, W, a);
    dim3 g2(NN / TI, BB);
    gat_attn_kernel<<<g2, TI>>>(adj, mask, out);
}

// round 3
// speedup vs baseline: 1.3861x; 1.3861x over previous
#include <cuda_runtime.h>

// Problem shapes (fixed by the dataset)
#define BB   16
#define NN   2048
#define FIN  128
#define FO   64
#define TI   128       // i-rows per block
#define TJ   64        // j-tile
#define SPLITS 4       // j-dimension split factor
#define ALPHA 0.2f

// Scratch (allocation-free rule: __device__ globals)
__device__ float g_Wh[BB * NN * FO];               // 8 MB
__device__ float g_fi[BB * NN];
__device__ float g_fj[BB * NN];
__device__ float g_part[SPLITS * BB * NN * FO];    // 32 MB partial accumulators
__device__ float g_rsum[SPLITS * BB * NN];         // partial row sums

// ---- packed f32x2 helpers (sm_103a FFMA2: 2x fp32 FMA throughput) ----
__device__ __forceinline__ void fma2(unsigned long long& d,
                                     unsigned long long a,
                                     unsigned long long b) {
    asm("fma.rn.f32x2 %0, %1, %2, %0;" : "+l"(d) : "l"(a), "l"(b));
}
__device__ __forceinline__ unsigned long long pack2(float x, float y) {
    unsigned long long r;
    asm("mov.b64 %0, {%1, %2};" : "=l"(r) : "f"(x), "f"(y));
    return r;
}
__device__ __forceinline__ float2 unpack2(unsigned long long v) {
    float2 r;
    asm("mov.b64 {%0, %1}, %2;" : "=f"(r.x), "=f"(r.y) : "l"(v));
    return r;
}

// ============================================================
// Kernel 1: Wh = h @ W  (and f_i = Wh@a_src, f_j = Wh@a_dst)
// ============================================================
__global__ __launch_bounds__(256)
void gat_wh_kernel(const float* __restrict__ h,
                   const float* __restrict__ W,
                   const float* __restrict__ a) {
    __shared__ float h_s[16 * FIN];    // 8 KB
    __shared__ float W_s[FIN * FO];    // 32 KB

    int tid = threadIdx.x;
    size_t base = (size_t)blockIdx.x * 16;

    {
        const float4* hsrc = (const float4*)(h + base * FIN);
        float4* hdst = (float4*)h_s;
        #pragma unroll
        for (int r = 0; r < 2; r++) hdst[r * 256 + tid] = hsrc[r * 256 + tid];
        const float4* wsrc = (const float4*)W;
        float4* wdst = (float4*)W_s;
        #pragma unroll
        for (int r = 0; r < 8; r++) wdst[r * 256 + tid] = wsrc[r * 256 + tid];
    }
    __syncthreads();

    int r  = tid >> 4;
    int og = tid & 15;

    unsigned long long acc0 = 0ull, acc1 = 0ull;
    const float* hrow = h_s + r * FIN;
    #pragma unroll 8
    for (int k = 0; k < FIN; k++) {
        float hv = hrow[k];
        unsigned long long hv2 = pack2(hv, hv);
        const ulonglong2* wp = (const ulonglong2*)(W_s + k * FO + og * 4);
        ulonglong2 w = *wp;
        fma2(acc0, hv2, w.x);
        fma2(acc1, hv2, w.y);
    }
    float2 a01 = unpack2(acc0), a23 = unpack2(acc1);

    size_t row = base + r;
    float4 v = make_float4(a01.x, a01.y, a23.x, a23.y);
    ((float4*)(g_Wh + row * FO))[og] = v;

    int o = og * 4;
    float ps = a01.x * a[o]      + a01.y * a[o + 1]      + a23.x * a[o + 2]      + a23.y * a[o + 3];
    float pd = a01.x * a[FO + o] + a01.y * a[FO + o + 1] + a23.x * a[FO + o + 2] + a23.y * a[FO + o + 3];
    #pragma unroll
    for (int off = 8; off >= 1; off >>= 1) {
        ps += __shfl_down_sync(0xffffffffu, ps, off, 16);
        pd += __shfl_down_sync(0xffffffffu, pd, off, 16);
    }
    if (og == 0) { g_fi[row] = ps; g_fj[row] = pd; }
}

// ============================================================
// Kernel 2: fused masked-softmax attention + partial P@Wh
// grid = (N/TI, B, SPLITS), block = 256 threads.
// Thread t accumulates row (t&127), f-half (t>>7) over its j-split.
// ============================================================
__global__ __launch_bounds__(256, 3)
void gat_attn_kernel(const float* __restrict__ adj,
                     const float* __restrict__ mask,
                     float* __restrict__ part,
                     float* __restrict__ rsum) {
    __shared__ float Wh_s[TJ * FO];   // 16 KB
    __shared__ float p_s[TI * TJ];    // 32 KB (XOR-swizzled)

    int tid = threadIdx.x;
    int b   = blockIdx.y;
    int i0  = blockIdx.x * TI;
    int s   = blockIdx.z;
    int jbeg = s * (NN / SPLITS);
    int jend = jbeg + (NN / SPLITS);

    const float* adj_b  = adj  + (size_t)b * NN * NN;
    const float* mask_b = mask + (size_t)b * NN;
    const float* Wh_b   = g_Wh + (size_t)b * NN * FO;
    const float* fi_b   = g_fi + (size_t)b * NN;
    const float* fj_b   = g_fj + (size_t)b * NN;

    int jfix = tid & 63;     // p-stage: fixed j-column
    int ish  = tid >> 6;     // 0..3 (constant per warp)
    int row  = tid & 127;    // accumulate-stage: output row
    int fh   = tid >> 7;     // 0/1: f-half of output row

    unsigned long long acc[16];
    #pragma unroll
    for (int q = 0; q < 16; q++) acc[q] = 0ull;
    float rowsum = 0.f;

    for (int j0 = jbeg; j0 < jend; j0 += TJ) {
        __syncthreads();

        // stage Wh tile (coalesced): 64x64 floats = 1024 float4
        {
            const float4* src = (const float4*)(Wh_b + (size_t)j0 * FO);
            float4* dst = (float4*)Wh_s;
            #pragma unroll
            for (int r2 = 0; r2 < 4; r2++) dst[r2 * 256 + tid] = src[r2 * 256 + tid];
        }

        // compute p tile: p = active ? exp(leakyrelu(fi+fj)) : 0
        float fjv = fj_b[j0 + jfix];
        float mj  = mask_b[j0 + jfix];
        bool  jok = (mj > 0.f);
        const float* adj_col = adj_b + (size_t)i0 * NN + j0 + jfix;
        #pragma unroll 4
        for (int rep = 0; rep < 32; rep++) {
            int il = 4 * rep + ish;
            float av  = adj_col[(size_t)il * NN];
            float fiv = fi_b[i0 + il];
            float miv = mask_b[i0 + il];
            float x  = fiv + fjv;
            float l  = fmaxf(x, ALPHA * x);
            float pe = __expf(l);
            float p  = (av > 0.f && jok && miv > 0.f) ? pe : 0.f;
            p_s[il * TJ + (jfix ^ (il & 31))] = p;
        }
        __syncthreads();

        // accumulate: acc covers 32 floats (16 x f32x2) of this thread's f-half
        int sw = row & 31;
        const float* prow  = p_s + row * TJ;
        const float* whbas = Wh_s + fh * 32;
        #pragma unroll 4
        for (int j = 0; j < TJ; j++) {
            float p = prow[j ^ sw];
            rowsum += p;
            unsigned long long p2 = pack2(p, p);
            const ulonglong2* wp = (const ulonglong2*)(whbas + j * FO);
            #pragma unroll
            for (int f = 0; f < 8; f++) {
                ulonglong2 w = wp[f];
                fma2(acc[2 * f],     p2, w.x);
                fma2(acc[2 * f + 1], p2, w.y);
            }
        }
    }

    // write ALL 16 f32x2 partials (32 floats) for this f-half
    size_t prow_idx = (size_t)s * BB * NN + (size_t)b * NN + i0 + row;
    float2* pp2 = (float2*)(part + prow_idx * FO + fh * 32);
    #pragma unroll
    for (int f = 0; f < 16; f++) pp2[f] = unpack2(acc[f]);
    if (fh == 0) rsum[prow_idx] = rowsum;
}

// ============================================================
// Kernel 3: reduce splits, normalize, relu
// ============================================================
__global__ __launch_bounds__(256)
void gat_reduce_kernel(const float* __restrict__ part,
                       const float* __restrict__ rsum,
                       float* __restrict__ out) {
    int t = blockIdx.x * blockDim.x + threadIdx.x;   // [0, BB*NN*16)
    int rowi = t >> 4;

    float rs = 0.f;
    #pragma unroll
    for (int s = 0; s < SPLITS; s++) rs += rsum[(size_t)s * BB * NN + rowi];
    float inv = (rs > 0.f) ? (1.f / rs) : 0.f;

    float4 v = make_float4(0.f, 0.f, 0.f, 0.f);
    #pragma unroll
    for (int s = 0; s < SPLITS; s++) {
        float4 pv = ((const float4*)part)[(size_t)s * BB * NN * 16 + t];
        v.x += pv.x; v.y += pv.y; v.z += pv.z; v.w += pv.w;
    }
    float4 o;
    o.x = fmaxf(v.x * inv, 0.f);
    o.y = fmaxf(v.y * inv, 0.f);
    o.z = fmaxf(v.z * inv, 0.f);
    o.w = fmaxf(v.w * inv, 0.f);
    ((float4*)out)[t] = o;
}

// ============================================================
extern "C" void kernel_launch(void* const* d_in, const int* in_sizes, int n_in,
                              void* d_out, int out_size) {
    const float *h = nullptr, *adj = nullptr, *mask = nullptr, *W = nullptr, *a = nullptr;
    for (int i = 0; i < n_in; i++) {
        switch (in_sizes[i]) {
            case BB * NN * FIN:  h    = (const float*)d_in[i]; break;
            case BB * NN * NN:   adj  = (const float*)d_in[i]; break;
            case BB * NN:        mask = (const float*)d_in[i]; break;
            case FIN * FO:       W    = (const float*)d_in[i]; break;
            case 2 * FO:         a    = (const float*)d_in[i]; break;
        }
    }
    float* out = (float*)d_out;

    float* part; cudaGetSymbolAddress((void**)&part, g_part);
    float* rsum; cudaGetSymbolAddress((void**)&rsum, g_rsum);

    gat_wh_kernel<<<BB * NN / 16, 256>>>(h, W, a);
    dim3 g2(NN / TI, BB, SPLITS);
    gat_attn_kernel<<<g2, 256>>>(adj, mask, part, rsum);
    gat_reduce_kernel<<<BB * NN * 16 / 256, 256>>>(part, rsum, out);
}

// round 4
// speedup vs baseline: 2.1873x; 1.5780x over previous
#include <cuda_runtime.h>

// Problem shapes (fixed by the dataset)
#define BB   16
#define NN   2048
#define FIN  128
#define FO   64
#define TI   128       // i-rows per block
#define TJ   64        // j-tile
#define SPLITS 4       // j-dimension split factor
#define ALPHA 0.2f

// Scratch (allocation-free rule: __device__ globals)
__device__ float g_Wh[BB * NN * FO];               // 8 MB
__device__ float g_fi[BB * NN];
__device__ float g_fj[BB * NN];
__device__ float g_part[SPLITS * BB * NN * FO];    // 32 MB partial accumulators
__device__ float g_rsum[SPLITS * BB * NN];         // partial row sums

// ---- packed f32x2 helpers (sm_103a FFMA2: 2x fp32 FMA throughput) ----
__device__ __forceinline__ void fma2(unsigned long long& d,
                                     unsigned long long a,
                                     unsigned long long b) {
    asm("fma.rn.f32x2 %0, %1, %2, %0;" : "+l"(d) : "l"(a), "l"(b));
}
__device__ __forceinline__ unsigned long long pack2(float x, float y) {
    unsigned long long r;
    asm("mov.b64 %0, {%1, %2};" : "=l"(r) : "f"(x), "f"(y));
    return r;
}
__device__ __forceinline__ float2 unpack2(unsigned long long v) {
    float2 r;
    asm("mov.b64 {%0, %1}, %2;" : "=f"(r.x), "=f"(r.y) : "l"(v));
    return r;
}

// ============================================================
// Kernel 1: Wh = h @ W  (and f_i = Wh@a_src, f_j = Wh@a_dst)
// ============================================================
__global__ __launch_bounds__(256)
void gat_wh_kernel(const float* __restrict__ h,
                   const float* __restrict__ W,
                   const float* __restrict__ a) {
    __shared__ float h_s[16 * FIN];    // 8 KB
    __shared__ float W_s[FIN * FO];    // 32 KB

    int tid = threadIdx.x;
    size_t base = (size_t)blockIdx.x * 16;

    {
        const float4* hsrc = (const float4*)(h + base * FIN);
        float4* hdst = (float4*)h_s;
        #pragma unroll
        for (int r = 0; r < 2; r++) hdst[r * 256 + tid] = hsrc[r * 256 + tid];
        const float4* wsrc = (const float4*)W;
        float4* wdst = (float4*)W_s;
        #pragma unroll
        for (int r = 0; r < 8; r++) wdst[r * 256 + tid] = wsrc[r * 256 + tid];
    }
    __syncthreads();

    int r  = tid >> 4;
    int og = tid & 15;

    unsigned long long acc0 = 0ull, acc1 = 0ull;
    const float* hrow = h_s + r * FIN;
    #pragma unroll 4
    for (int k = 0; k < FIN; k += 4) {
        float4 hv4 = *(const float4*)(hrow + k);      // 1 LDS.128 per 4 k
        #pragma unroll
        for (int t = 0; t < 4; t++) {
            float hv = (t == 0) ? hv4.x : (t == 1) ? hv4.y : (t == 2) ? hv4.z : hv4.w;
            unsigned long long hv2 = pack2(hv, hv);
            const ulonglong2* wp = (const ulonglong2*)(W_s + (k + t) * FO + og * 4);
            ulonglong2 w = *wp;
            fma2(acc0, hv2, w.x);
            fma2(acc1, hv2, w.y);
        }
    }
    float2 a01 = unpack2(acc0), a23 = unpack2(acc1);

    size_t row = base + r;
    float4 v = make_float4(a01.x, a01.y, a23.x, a23.y);
    ((float4*)(g_Wh + row * FO))[og] = v;

    int o = og * 4;
    float ps = a01.x * a[o]      + a01.y * a[o + 1]      + a23.x * a[o + 2]      + a23.y * a[o + 3];
    float pd = a01.x * a[FO + o] + a01.y * a[FO + o + 1] + a23.x * a[FO + o + 2] + a23.y * a[FO + o + 3];
    #pragma unroll
    for (int off = 8; off >= 1; off >>= 1) {
        ps += __shfl_down_sync(0xffffffffu, ps, off, 16);
        pd += __shfl_down_sync(0xffffffffu, pd, off, 16);
    }
    if (og == 0) { g_fi[row] = ps; g_fj[row] = pd; }
}

// ============================================================
// Kernel 2: fused masked-softmax attention + partial P@Wh
// grid = (N/TI, B, SPLITS), block = 512 threads.
// Thread t owns row (t&127), f-QUARTER (t>>7): 16 floats = 8 f32x2 acc.
// 50% occupancy target (2 blocks/SM); cross-block overlap hides the
// adj-load (DRAM) latency of the p-stage.
// ============================================================
__global__ __launch_bounds__(512, 2)
void gat_attn_kernel(const float* __restrict__ adj,
                     const float* __restrict__ mask,
                     float* __restrict__ part,
                     float* __restrict__ rsum) {
    __shared__ float Wh_s[TJ * FO];   // 16 KB
    __shared__ float p_s[TI * TJ];    // 32 KB (XOR-swizzled)

    int tid = threadIdx.x;
    int b   = blockIdx.y;
    int i0  = blockIdx.x * TI;
    int s   = blockIdx.z;
    int jbeg = s * (NN / SPLITS);
    int jend = jbeg + (NN / SPLITS);

    const float* adj_b  = adj  + (size_t)b * NN * NN;
    const float* mask_b = mask + (size_t)b * NN;
    const float* Wh_b   = g_Wh + (size_t)b * NN * FO;
    const float* fi_b   = g_fi + (size_t)b * NN;
    const float* fj_b   = g_fj + (size_t)b * NN;

    int jfix = tid & 63;     // p-stage: fixed j-column
    int ish  = tid >> 6;     // 0..7 (uniform per warp)
    int row  = tid & 127;    // accumulate-stage: output row
    int q    = tid >> 7;     // 0..3: f-quarter of output row

    unsigned long long acc[8];
    #pragma unroll
    for (int z = 0; z < 8; z++) acc[z] = 0ull;
    float rowsum = 0.f;

    for (int j0 = jbeg; j0 < jend; j0 += TJ) {
        __syncthreads();

        // stage Wh tile (coalesced): 64x64 floats = 1024 float4
        {
            const float4* src = (const float4*)(Wh_b + (size_t)j0 * FO);
            float4* dst = (float4*)Wh_s;
            #pragma unroll
            for (int r2 = 0; r2 < 2; r2++) dst[r2 * 512 + tid] = src[r2 * 512 + tid];
        }

        // compute p tile: p = active ? exp(leakyrelu(fi+fj)) : 0
        // 8192 entries / 512 threads = 16 per thread
        float fjv = fj_b[j0 + jfix];
        float mj  = mask_b[j0 + jfix];
        bool  jok = (mj > 0.f);
        const float* adj_col = adj_b + (size_t)i0 * NN + j0 + jfix;
        #pragma unroll 4
        for (int rep = 0; rep < 16; rep++) {
            int il = 8 * rep + ish;
            float av  = adj_col[(size_t)il * NN];
            float fiv = fi_b[i0 + il];
            float miv = mask_b[i0 + il];
            float x  = fiv + fjv;
            float l  = fmaxf(x, ALPHA * x);
            float pe = __expf(l);
            float p  = (av > 0.f && jok && miv > 0.f) ? pe : 0.f;
            p_s[il * TJ + (jfix ^ (il & 31))] = p;
        }
        __syncthreads();

        // accumulate: 8 f32x2 (16 floats) of this thread's f-quarter
        int sw = row & 31;
        const float* prow  = p_s + row * TJ;
        const float* whbas = Wh_s + q * 16;
        #pragma unroll 2
        for (int j = 0; j < TJ; j++) {
            float p = prow[j ^ sw];
            rowsum += p;
            unsigned long long p2 = pack2(p, p);
            const ulonglong2* wp = (const ulonglong2*)(whbas + j * FO);
            #pragma unroll
            for (int f = 0; f < 4; f++) {
                ulonglong2 w = wp[f];
                fma2(acc[2 * f],     p2, w.x);
                fma2(acc[2 * f + 1], p2, w.y);
            }
        }
    }

    // write the 8 f32x2 partials (16 floats) of this f-quarter
    size_t prow_idx = (size_t)s * BB * NN + (size_t)b * NN + i0 + row;
    float2* pp2 = (float2*)(part + prow_idx * FO + q * 16);
    #pragma unroll
    for (int f = 0; f < 8; f++) pp2[f] = unpack2(acc[f]);
    if (q == 0) rsum[prow_idx] = rowsum;
}

// ============================================================
// Kernel 3: reduce splits, normalize, relu
// ============================================================
__global__ __launch_bounds__(256)
void gat_reduce_kernel(const float* __restrict__ part,
                       const float* __restrict__ rsum,
                       float* __restrict__ out) {
    int t = blockIdx.x * blockDim.x + threadIdx.x;   // [0, BB*NN*16)
    int rowi = t >> 4;

    float rs = 0.f;
    #pragma unroll
    for (int s = 0; s < SPLITS; s++) rs += rsum[(size_t)s * BB * NN + rowi];
    float inv = (rs > 0.f) ? (1.f / rs) : 0.f;

    float4 v = make_float4(0.f, 0.f, 0.f, 0.f);
    #pragma unroll
    for (int s = 0; s < SPLITS; s++) {
        float4 pv = ((const float4*)part)[(size_t)s * BB * NN * 16 + t];
        v.x += pv.x; v.y += pv.y; v.z += pv.z; v.w += pv.w;
    }
    float4 o;
    o.x = fmaxf(v.x * inv, 0.f);
    o.y = fmaxf(v.y * inv, 0.f);
    o.z = fmaxf(v.z * inv, 0.f);
    o.w = fmaxf(v.w * inv, 0.f);
    ((float4*)out)[t] = o;
}

// ============================================================
extern "C" void kernel_launch(void* const* d_in, const int* in_sizes, int n_in,
                              void* d_out, int out_size) {
    const float *h = nullptr, *adj = nullptr, *mask = nullptr, *W = nullptr, *a = nullptr;
    for (int i = 0; i < n_in; i++) {
        switch (in_sizes[i]) {
            case BB * NN * FIN:  h    = (const float*)d_in[i]; break;
            case BB * NN * NN:   adj  = (const float*)d_in[i]; break;
            case BB * NN:        mask = (const float*)d_in[i]; break;
            case FIN * FO:       W    = (const float*)d_in[i]; break;
            case 2 * FO:         a    = (const float*)d_in[i]; break;
        }
    }
    float* out = (float*)d_out;

    float* part; cudaGetSymbolAddress((void**)&part, g_part);
    float* rsum; cudaGetSymbolAddress((void**)&rsum, g_rsum);

    gat_wh_kernel<<<BB * NN / 16, 256>>>(h, W, a);
    dim3 g2(NN / TI, BB, SPLITS);
    gat_attn_kernel<<<g2, 512>>>(adj, mask, part, rsum);
    gat_reduce_kernel<<<BB * NN * 16 / 256, 256>>>(part, rsum, out);
}

// round 5
// speedup vs baseline: 2.3281x; 1.0644x over previous
#include <cuda_runtime.h>

// Problem shapes (fixed by the dataset)
#define BB   16
#define NN   2048
#define FIN  128
#define FO   64
#define TI   128       // i-rows per block
#define TJ   64        // j-tile
#define SPLITS 8       // j-dimension split factor
#define NTILES (NN / SPLITS / TJ)   // 4
#define ALPHA 0.2f

// Scratch (allocation-free rule: __device__ globals)
__device__ float g_Wh[BB * NN * FO];               // 8 MB
__device__ float g_fi[BB * NN];                    // mask pre-folded
__device__ float g_fj[BB * NN];
__device__ float g_part[SPLITS * BB * NN * FO];    // 64 MB partial accumulators
__device__ float g_rsum[SPLITS * BB * NN];         // partial row sums

// ---- packed f32x2 helpers ----
__device__ __forceinline__ void fma2(unsigned long long& d,
                                     unsigned long long a,
                                     unsigned long long b) {
    asm("fma.rn.f32x2 %0, %1, %2, %0;" : "+l"(d) : "l"(a), "l"(b));
}
__device__ __forceinline__ unsigned long long pack2(float x, float y) {
    unsigned long long r;
    asm("mov.b64 %0, {%1, %2};" : "=l"(r) : "f"(x), "f"(y));
    return r;
}
__device__ __forceinline__ float2 unpack2(unsigned long long v) {
    float2 r;
    asm("mov.b64 {%0, %1}, %2;" : "=f"(r.x), "=f"(r.y) : "l"(v));
    return r;
}

// ---- cp.async helpers ----
__device__ __forceinline__ void cpasync4(unsigned smem_addr, const float* g) {
    asm volatile("cp.async.ca.shared.global [%0], [%1], 4;" :: "r"(smem_addr), "l"(g) : "memory");
}
__device__ __forceinline__ void cpasync16(unsigned smem_addr, const float4* g) {
    asm volatile("cp.async.cg.shared.global [%0], [%1], 16;" :: "r"(smem_addr), "l"(g) : "memory");
}
__device__ __forceinline__ void cpasync_commit() {
    asm volatile("cp.async.commit_group;" ::: "memory");
}
__device__ __forceinline__ void cpasync_wait0() {
    asm volatile("cp.async.wait_group 0;" ::: "memory");
}

// ============================================================
// Kernel 1: Wh = h @ W  (+ masked f_i, f_j). 2 rows/thread to
// share W LDS.128 loads (crossbar was the bottleneck: L1=85%).
// block 256 = 16 og x 16 r; rows r and r+16 (32 rows/block).
// ============================================================
__global__ __launch_bounds__(256)
void gat_wh_kernel(const float* __restrict__ h,
                   const float* __restrict__ W,
                   const float* __restrict__ a,
                   const float* __restrict__ mask) {
    __shared__ float h_s[32 * FIN];    // 16 KB
    __shared__ float W_s[FIN * FO];    // 32 KB

    int tid = threadIdx.x;
    size_t base = (size_t)blockIdx.x * 32;

    {
        const float4* hsrc = (const float4*)(h + base * FIN);
        float4* hdst = (float4*)h_s;
        #pragma unroll
        for (int r = 0; r < 4; r++) hdst[r * 256 + tid] = hsrc[r * 256 + tid];
        const float4* wsrc = (const float4*)W;
        float4* wdst = (float4*)W_s;
        #pragma unroll
        for (int r = 0; r < 8; r++) wdst[r * 256 + tid] = wsrc[r * 256 + tid];
    }
    __syncthreads();

    int r  = tid >> 4;        // 0..15 -> rows r, r+16
    int og = tid & 15;

    unsigned long long acc0 = 0ull, acc1 = 0ull, acc2 = 0ull, acc3 = 0ull;
    const float* hrowA = h_s + r * FIN;
    const float* hrowB = h_s + (r + 16) * FIN;
    #pragma unroll 4
    for (int k = 0; k < FIN; k += 4) {
        float4 ha = *(const float4*)(hrowA + k);
        float4 hb = *(const float4*)(hrowB + k);
        #pragma unroll
        for (int t = 0; t < 4; t++) {
            float va = (t == 0) ? ha.x : (t == 1) ? ha.y : (t == 2) ? ha.z : ha.w;
            float vb = (t == 0) ? hb.x : (t == 1) ? hb.y : (t == 2) ? hb.z : hb.w;
            ulonglong2 w = *(const ulonglong2*)(W_s + (k + t) * FO + og * 4);
            unsigned long long va2 = pack2(va, va);
            unsigned long long vb2 = pack2(vb, vb);
            fma2(acc0, va2, w.x);
            fma2(acc1, va2, w.y);
            fma2(acc2, vb2, w.x);
            fma2(acc3, vb2, w.y);
        }
    }

    int o = og * 4;
    #pragma unroll
    for (int half = 0; half < 2; half++) {
        float2 p01 = unpack2(half ? acc2 : acc0);
        float2 p23 = unpack2(half ? acc3 : acc1);
        size_t row = base + r + half * 16;
        ((float4*)(g_Wh + row * FO))[og] = make_float4(p01.x, p01.y, p23.x, p23.y);

        float ps = p01.x * a[o]      + p01.y * a[o + 1]      + p23.x * a[o + 2]      + p23.y * a[o + 3];
        float pd = p01.x * a[FO + o] + p01.y * a[FO + o + 1] + p23.x * a[FO + o + 2] + p23.y * a[FO + o + 3];
        #pragma unroll
        for (int off = 8; off >= 1; off >>= 1) {
            ps += __shfl_down_sync(0xffffffffu, ps, off, 16);
            pd += __shfl_down_sync(0xffffffffu, pd, off, 16);
        }
        if (og == 0) {
            bool ok = mask[row] > 0.f;          // fold node mask: exp(-inf)->0
            g_fi[row] = ok ? ps : -1e30f;
            g_fj[row] = ok ? pd : -1e30f;
        }
    }
}

// ============================================================
// Kernel 2: fused masked-softmax attention + partial P@Wh.
// cp.async software pipeline: adj(t+1), Wh(t+1) land during
// accumulate(t). Dynamic smem: p_s 32K + adjbuf 32K + whbuf 2x16K = 96K.
// ============================================================
__global__ __launch_bounds__(512, 2)
void gat_attn_kernel(const float* __restrict__ adj,
                     float* __restrict__ part,
                     float* __restrict__ rsum) {
    extern __shared__ float smem[];
    float* p_s    = smem;                    // [TI*TJ]  swizzled
    float* adjbuf = smem + TI * TJ;          // [TI*TJ]
    float* whbuf  = smem + 2 * TI * TJ;      // [2][TJ*FO]

    int tid = threadIdx.x;
    int b   = blockIdx.y;
    int i0  = blockIdx.x * TI;
    int s   = blockIdx.z;
    int jbeg = s * (NN / SPLITS);

    const float* adj_b = adj  + (size_t)b * NN * NN;
    const float* Wh_b  = g_Wh + (size_t)b * NN * FO;
    const float* fi_b  = g_fi + (size_t)b * NN;
    const float* fj_b  = g_fj + (size_t)b * NN;

    int jfix = tid & 63;     // p-stage: fixed j-column
    int ish  = tid >> 6;     // 0..7 (uniform per warp)
    int row  = tid & 127;    // accumulate-stage: output row
    int q    = tid >> 7;     // 0..3: f-quarter

    unsigned adjbuf_u = (unsigned)__cvta_generic_to_shared(adjbuf);
    unsigned whbuf_u  = (unsigned)__cvta_generic_to_shared(whbuf);

    unsigned long long acc[8];
    #pragma unroll
    for (int z = 0; z < 8; z++) acc[z] = 0ull;
    float rowsum = 0.f;

    // ---- prologue: async-fetch tile 0 ----
    {
        const float* acol = adj_b + (size_t)i0 * NN + jbeg + jfix;
        #pragma unroll
        for (int rep = 0; rep < 16; rep++) {
            int il = 8 * rep + ish;
            cpasync4(adjbuf_u + (il * TJ + jfix) * 4, acol + (size_t)il * NN);
        }
        const float4* src = (const float4*)(Wh_b + (size_t)jbeg * FO);
        #pragma unroll
        for (int r2 = 0; r2 < 2; r2++)
            cpasync16(whbuf_u + (r2 * 512 + tid) * 16, src + r2 * 512 + tid);
        cpasync_commit();
    }

    float fjv = fj_b[jbeg + jfix];   // first tile's fj (reloaded per tile below)

    for (int t = 0; t < NTILES; t++) {
        int cur = t & 1;
        int j0  = jbeg + t * TJ;

        cpasync_wait0();
        __syncthreads();             // arrivals visible to all; p_s free

        // ---- compute p(t): adjbuf -> p_s (swizzled) ----
        fjv = fj_b[j0 + jfix];
        #pragma unroll 4
        for (int rep = 0; rep < 16; rep++) {
            int il  = 8 * rep + ish;
            float av  = adjbuf[il * TJ + jfix];
            float fiv = fi_b[i0 + il];
            float x   = fiv + fjv;
            float l   = fmaxf(x, ALPHA * x);
            float pe  = __expf(l);
            float p   = (av > 0.f) ? pe : 0.f;
            p_s[il * TJ + (jfix ^ (il & 31))] = p;
        }
        __syncthreads();             // p_s ready; adjbuf consumed

        // ---- issue async-fetch of tile t+1 (overlaps accumulate) ----
        if (t + 1 < NTILES) {
            int j0n = j0 + TJ;
            const float* acol = adj_b + (size_t)i0 * NN + j0n + jfix;
            #pragma unroll
            for (int rep = 0; rep < 16; rep++) {
                int il = 8 * rep + ish;
                cpasync4(adjbuf_u + (il * TJ + jfix) * 4, acol + (size_t)il * NN);
            }
            const float4* src = (const float4*)(Wh_b + (size_t)j0n * FO);
            unsigned dst = whbuf_u + (1 - cur) * TJ * FO * 4;
            #pragma unroll
            for (int r2 = 0; r2 < 2; r2++)
                cpasync16(dst + (r2 * 512 + tid) * 16, src + r2 * 512 + tid);
            cpasync_commit();
        }

        // ---- accumulate(t): 8 f32x2 of this thread's f-quarter ----
        int sw = row & 31;
        const float* prow  = p_s + row * TJ;
        const float* whbas = whbuf + cur * TJ * FO + q * 16;
        #pragma unroll 2
        for (int j = 0; j < TJ; j++) {
            float p = prow[j ^ sw];
            rowsum += p;
            unsigned long long p2 = pack2(p, p);
            const ulonglong2* wp = (const ulonglong2*)(whbas + j * FO);
            #pragma unroll
            for (int f = 0; f < 4; f++) {
                ulonglong2 w = wp[f];
                fma2(acc[2 * f],     p2, w.x);
                fma2(acc[2 * f + 1], p2, w.y);
            }
        }
        __syncthreads();             // p_s/whbuf[cur] free for next tile
    }

    size_t prow_idx = (size_t)s * BB * NN + (size_t)b * NN + i0 + row;
    float2* pp2 = (float2*)(part + prow_idx * FO + q * 16);
    #pragma unroll
    for (int f = 0; f < 8; f++) pp2[f] = unpack2(acc[f]);
    if (q == 0) rsum[prow_idx] = rowsum;
}

// ============================================================
// Kernel 3: reduce splits, normalize, relu
// ============================================================
__global__ __launch_bounds__(256)
void gat_reduce_kernel(const float* __restrict__ part,
                       const float* __restrict__ rsum,
                       float* __restrict__ out) {
    int t = blockIdx.x * blockDim.x + threadIdx.x;   // [0, BB*NN*16)
    int rowi = t >> 4;

    float rs = 0.f;
    #pragma unroll
    for (int s = 0; s < SPLITS; s++) rs += rsum[(size_t)s * BB * NN + rowi];
    float inv = (rs > 0.f) ? (1.f / rs) : 0.f;

    float4 v = make_float4(0.f, 0.f, 0.f, 0.f);
    #pragma unroll
    for (int s = 0; s < SPLITS; s++) {
        float4 pv = ((const float4*)part)[(size_t)s * BB * NN * 16 + t];
        v.x += pv.x; v.y += pv.y; v.z += pv.z; v.w += pv.w;
    }
    float4 o;
    o.x = fmaxf(v.x * inv, 0.f);
    o.y = fmaxf(v.y * inv, 0.f);
    o.z = fmaxf(v.z * inv, 0.f);
    o.w = fmaxf(v.w * inv, 0.f);
    ((float4*)out)[t] = o;
}

// ============================================================
extern "C" void kernel_launch(void* const* d_in, const int* in_sizes, int n_in,
                              void* d_out, int out_size) {
    const float *h = nullptr, *adj = nullptr, *mask = nullptr, *W = nullptr, *a = nullptr;
    for (int i = 0; i < n_in; i++) {
        switch (in_sizes[i]) {
            case BB * NN * FIN:  h    = (const float*)d_in[i]; break;
            case BB * NN * NN:   adj  = (const float*)d_in[i]; break;
            case BB * NN:        mask = (const float*)d_in[i]; break;
            case FIN * FO:       W    = (const float*)d_in[i]; break;
            case 2 * FO:         a    = (const float*)d_in[i]; break;
        }
    }
    float* out = (float*)d_out;

    float* part; cudaGetSymbolAddress((void**)&part, g_part);
    float* rsum; cudaGetSymbolAddress((void**)&rsum, g_rsum);

    static bool attr_set = false;
    if (!attr_set) {
        cudaFuncSetAttribute(gat_attn_kernel,
                             cudaFuncAttributeMaxDynamicSharedMemorySize, 96 * 1024);
        attr_set = true;
    }

    gat_wh_kernel<<<BB * NN / 32, 256>>>(h, W, a, mask);
    dim3 g2(NN / TI, BB, SPLITS);
    gat_attn_kernel<<<g2, 512, 96 * 1024>>>(adj, part, rsum);
    gat_reduce_kernel<<<BB * NN * 16 / 256, 256>>>(part, rsum, out);
}

// round 6
// speedup vs baseline: 2.3328x; 1.0020x over previous
#include <cuda_runtime.h>

// Problem shapes (fixed by the dataset)
#define BB   16
#define NN   2048
#define FIN  128
#define FO   64
#define TI   128       // i-rows per block
#define TJ   64        // j-tile
#define SPLITS 8       // j-dimension split factor
#define NTILES (NN / SPLITS / TJ)   // 4
#define ALPHA 0.2f

// Scratch (allocation-free rule: __device__ globals)
__device__ float g_Wh[BB * NN * FO];               // 8 MB
__device__ float g_fi[BB * NN];                    // mask pre-folded
__device__ float g_fj[BB * NN];
__device__ float g_part[SPLITS * BB * NN * FO];    // 64 MB partial accumulators
__device__ float g_rsum[SPLITS * BB * NN];         // partial row sums

// ---- packed f32x2 helpers ----
__device__ __forceinline__ void fma2(unsigned long long& d,
                                     unsigned long long a,
                                     unsigned long long b) {
    asm("fma.rn.f32x2 %0, %1, %2, %0;" : "+l"(d) : "l"(a), "l"(b));
}
__device__ __forceinline__ unsigned long long pack2(float x, float y) {
    unsigned long long r;
    asm("mov.b64 %0, {%1, %2};" : "=l"(r) : "f"(x), "f"(y));
    return r;
}
__device__ __forceinline__ float2 unpack2(unsigned long long v) {
    float2 r;
    asm("mov.b64 {%0, %1}, %2;" : "=f"(r.x), "=f"(r.y) : "l"(v));
    return r;
}

// ---- cp.async helpers ----
__device__ __forceinline__ void cpasync4(unsigned smem_addr, const float* g) {
    asm volatile("cp.async.ca.shared.global [%0], [%1], 4;" :: "r"(smem_addr), "l"(g) : "memory");
}
__device__ __forceinline__ void cpasync16(unsigned smem_addr, const float4* g) {
    asm volatile("cp.async.cg.shared.global [%0], [%1], 16;" :: "r"(smem_addr), "l"(g) : "memory");
}
__device__ __forceinline__ void cpasync_commit() {
    asm volatile("cp.async.commit_group;" ::: "memory");
}
__device__ __forceinline__ void cpasync_wait0() {
    asm volatile("cp.async.wait_group 0;" ::: "memory");
}

// ============================================================
// Kernel 1: Wh = h @ W  (+ masked f_i, f_j). 2 rows/thread to
// share W LDS.128 loads (crossbar was the bottleneck: L1=85%).
// block 256 = 16 og x 16 r; rows r and r+16 (32 rows/block).
// ============================================================
__global__ __launch_bounds__(256)
void gat_wh_kernel(const float* __restrict__ h,
                   const float* __restrict__ W,
                   const float* __restrict__ a,
                   const float* __restrict__ mask) {
    __shared__ float h_s[32 * FIN];    // 16 KB
    __shared__ float W_s[FIN * FO];    // 32 KB

    int tid = threadIdx.x;
    size_t base = (size_t)blockIdx.x * 32;

    {
        const float4* hsrc = (const float4*)(h + base * FIN);
        float4* hdst = (float4*)h_s;
        #pragma unroll
        for (int r = 0; r < 4; r++) hdst[r * 256 + tid] = hsrc[r * 256 + tid];
        const float4* wsrc = (const float4*)W;
        float4* wdst = (float4*)W_s;
        #pragma unroll
        for (int r = 0; r < 8; r++) wdst[r * 256 + tid] = wsrc[r * 256 + tid];
    }
    __syncthreads();

    int r  = tid >> 4;        // 0..15 -> rows r, r+16
    int og = tid & 15;

    unsigned long long acc0 = 0ull, acc1 = 0ull, acc2 = 0ull, acc3 = 0ull;
    const float* hrowA = h_s + r * FIN;
    const float* hrowB = h_s + (r + 16) * FIN;
    #pragma unroll 4
    for (int k = 0; k < FIN; k += 4) {
        float4 ha = *(const float4*)(hrowA + k);
        float4 hb = *(const float4*)(hrowB + k);
        #pragma unroll
        for (int t = 0; t < 4; t++) {
            float va = (t == 0) ? ha.x : (t == 1) ? ha.y : (t == 2) ? ha.z : ha.w;
            float vb = (t == 0) ? hb.x : (t == 1) ? hb.y : (t == 2) ? hb.z : hb.w;
            ulonglong2 w = *(const ulonglong2*)(W_s + (k + t) * FO + og * 4);
            unsigned long long va2 = pack2(va, va);
            unsigned long long vb2 = pack2(vb, vb);
            fma2(acc0, va2, w.x);
            fma2(acc1, va2, w.y);
            fma2(acc2, vb2, w.x);
            fma2(acc3, vb2, w.y);
        }
    }

    int o = og * 4;
    #pragma unroll
    for (int half = 0; half < 2; half++) {
        float2 p01 = unpack2(half ? acc2 : acc0);
        float2 p23 = unpack2(half ? acc3 : acc1);
        size_t row = base + r + half * 16;
        ((float4*)(g_Wh + row * FO))[og] = make_float4(p01.x, p01.y, p23.x, p23.y);

        float ps = p01.x * a[o]      + p01.y * a[o + 1]      + p23.x * a[o + 2]      + p23.y * a[o + 3];
        float pd = p01.x * a[FO + o] + p01.y * a[FO + o + 1] + p23.x * a[FO + o + 2] + p23.y * a[FO + o + 3];
        #pragma unroll
        for (int off = 8; off >= 1; off >>= 1) {
            ps += __shfl_down_sync(0xffffffffu, ps, off, 16);
            pd += __shfl_down_sync(0xffffffffu, pd, off, 16);
        }
        if (og == 0) {
            bool ok = mask[row] > 0.f;          // fold node mask: exp(-inf)->0
            g_fi[row] = ok ? ps : -1e30f;
            g_fj[row] = ok ? pd : -1e30f;
        }
    }
}

// ============================================================
// Kernel 2: fused masked-softmax attention + partial P@Wh.
// cp.async software pipeline: adj(t+1), Wh(t+1) land during
// accumulate(t). Dynamic smem: p_s 32K + adjbuf 32K + whbuf 2x16K = 96K.
// ============================================================
__global__ __launch_bounds__(512, 2)
void gat_attn_kernel(const float* __restrict__ adj,
                     float* __restrict__ part,
                     float* __restrict__ rsum) {
    extern __shared__ float smem[];
    float* p_s    = smem;                    // [TI*TJ]  swizzled
    float* adjbuf = smem + TI * TJ;          // [TI*TJ]
    float* whbuf  = smem + 2 * TI * TJ;      // [2][TJ*FO]

    int tid = threadIdx.x;
    int b   = blockIdx.y;
    int i0  = blockIdx.x * TI;
    int s   = blockIdx.z;
    int jbeg = s * (NN / SPLITS);

    const float* adj_b = adj  + (size_t)b * NN * NN;
    const float* Wh_b  = g_Wh + (size_t)b * NN * FO;
    const float* fi_b  = g_fi + (size_t)b * NN;
    const float* fj_b  = g_fj + (size_t)b * NN;

    int jfix = tid & 63;     // p-stage: fixed j-column
    int ish  = tid >> 6;     // 0..7 (uniform per warp)
    int row  = tid & 127;    // accumulate-stage: output row
    int q    = tid >> 7;     // 0..3: f-quarter

    unsigned adjbuf_u = (unsigned)__cvta_generic_to_shared(adjbuf);
    unsigned whbuf_u  = (unsigned)__cvta_generic_to_shared(whbuf);

    unsigned long long acc[8];
    #pragma unroll
    for (int z = 0; z < 8; z++) acc[z] = 0ull;
    float rowsum = 0.f;

    // ---- prologue: async-fetch tile 0 ----
    {
        const float* acol = adj_b + (size_t)i0 * NN + jbeg + jfix;
        #pragma unroll
        for (int rep = 0; rep < 16; rep++) {
            int il = 8 * rep + ish;
            cpasync4(adjbuf_u + (il * TJ + jfix) * 4, acol + (size_t)il * NN);
        }
        const float4* src = (const float4*)(Wh_b + (size_t)jbeg * FO);
        #pragma unroll
        for (int r2 = 0; r2 < 2; r2++)
            cpasync16(whbuf_u + (r2 * 512 + tid) * 16, src + r2 * 512 + tid);
        cpasync_commit();
    }

    float fjv = fj_b[jbeg + jfix];   // first tile's fj (reloaded per tile below)

    for (int t = 0; t < NTILES; t++) {
        int cur = t & 1;
        int j0  = jbeg + t * TJ;

        cpasync_wait0();
        __syncthreads();             // arrivals visible to all; p_s free

        // ---- compute p(t): adjbuf -> p_s (swizzled) ----
        fjv = fj_b[j0 + jfix];
        #pragma unroll 4
        for (int rep = 0; rep < 16; rep++) {
            int il  = 8 * rep + ish;
            float av  = adjbuf[il * TJ + jfix];
            float fiv = fi_b[i0 + il];
            float x   = fiv + fjv;
            float l   = fmaxf(x, ALPHA * x);
            float pe  = __expf(l);
            float p   = (av > 0.f) ? pe : 0.f;
            p_s[il * TJ + (jfix ^ (il & 31))] = p;
        }
        __syncthreads();             // p_s ready; adjbuf consumed

        // ---- issue async-fetch of tile t+1 (overlaps accumulate) ----
        if (t + 1 < NTILES) {
            int j0n = j0 + TJ;
            const float* acol = adj_b + (size_t)i0 * NN + j0n + jfix;
            #pragma unroll
            for (int rep = 0; rep < 16; rep++) {
                int il = 8 * rep + ish;
                cpasync4(adjbuf_u + (il * TJ + jfix) * 4, acol + (size_t)il * NN);
            }
            const float4* src = (const float4*)(Wh_b + (size_t)j0n * FO);
            unsigned dst = whbuf_u + (1 - cur) * TJ * FO * 4;
            #pragma unroll
            for (int r2 = 0; r2 < 2; r2++)
                cpasync16(dst + (r2 * 512 + tid) * 16, src + r2 * 512 + tid);
            cpasync_commit();
        }

        // ---- accumulate(t): 8 f32x2 of this thread's f-quarter ----
        int sw = row & 31;
        const float* prow  = p_s + row * TJ;
        const float* whbas = whbuf + cur * TJ * FO + q * 16;
        #pragma unroll 2
        for (int j = 0; j < TJ; j++) {
            float p = prow[j ^ sw];
            rowsum += p;
            unsigned long long p2 = pack2(p, p);
            const ulonglong2* wp = (const ulonglong2*)(whbas + j * FO);
            #pragma unroll
            for (int f = 0; f < 4; f++) {
                ulonglong2 w = wp[f];
                fma2(acc[2 * f],     p2, w.x);
                fma2(acc[2 * f + 1], p2, w.y);
            }
        }
        __syncthreads();             // p_s/whbuf[cur] free for next tile
    }

    size_t prow_idx = (size_t)s * BB * NN + (size_t)b * NN + i0 + row;
    float2* pp2 = (float2*)(part + prow_idx * FO + q * 16);
    #pragma unroll
    for (int f = 0; f < 8; f++) pp2[f] = unpack2(acc[f]);
    if (q == 0) rsum[prow_idx] = rowsum;
}

// ============================================================
// Kernel 3: reduce splits, normalize, relu
// ============================================================
__global__ __launch_bounds__(256)
void gat_reduce_kernel(const float* __restrict__ part,
                       const float* __restrict__ rsum,
                       float* __restrict__ out) {
    int t = blockIdx.x * blockDim.x + threadIdx.x;   // [0, BB*NN*16)
    int rowi = t >> 4;

    float rs = 0.f;
    #pragma unroll
    for (int s = 0; s < SPLITS; s++) rs += rsum[(size_t)s * BB * NN + rowi];
    float inv = (rs > 0.f) ? (1.f / rs) : 0.f;

    float4 v = make_float4(0.f, 0.f, 0.f, 0.f);
    #pragma unroll
    for (int s = 0; s < SPLITS; s++) {
        float4 pv = ((const float4*)part)[(size_t)s * BB * NN * 16 + t];
        v.x += pv.x; v.y += pv.y; v.z += pv.z; v.w += pv.w;
    }
    float4 o;
    o.x = fmaxf(v.x * inv, 0.f);
    o.y = fmaxf(v.y * inv, 0.f);
    o.z = fmaxf(v.z * inv, 0.f);
    o.w = fmaxf(v.w * inv, 0.f);
    ((float4*)out)[t] = o;
}

// ============================================================
extern "C" void kernel_launch(void* const* d_in, const int* in_sizes, int n_in,
                              void* d_out, int out_size) {
    const float *h = nullptr, *adj = nullptr, *mask = nullptr, *W = nullptr, *a = nullptr;
    for (int i = 0; i < n_in; i++) {
        switch (in_sizes[i]) {
            case BB * NN * FIN:  h    = (const float*)d_in[i]; break;
            case BB * NN * NN:   adj  = (const float*)d_in[i]; break;
            case BB * NN:        mask = (const float*)d_in[i]; break;
            case FIN * FO:       W    = (const float*)d_in[i]; break;
            case 2 * FO:         a    = (const float*)d_in[i]; break;
        }
    }
    float* out = (float*)d_out;

    float* part; cudaGetSymbolAddress((void**)&part, g_part);
    float* rsum; cudaGetSymbolAddress((void**)&rsum, g_rsum);

    static bool attr_set = false;
    if (!attr_set) {
        cudaFuncSetAttribute(gat_attn_kernel,
                             cudaFuncAttributeMaxDynamicSharedMemorySize, 96 * 1024);
        attr_set = true;
    }

    gat_wh_kernel<<<BB * NN / 32, 256>>>(h, W, a, mask);
    dim3 g2(NN / TI, BB, SPLITS);
    gat_attn_kernel<<<g2, 512, 96 * 1024>>>(adj, part, rsum);
    gat_reduce_kernel<<<BB * NN * 16 / 256, 256>>>(part, rsum, out);
}

// round 8
// speedup vs baseline: 4.2919x; 1.8398x over previous
#include <cuda_runtime.h>
#include <cuda_bf16.h>

#define BB   16
#define NN   2048
#define FIN  128
#define FO   64
#define TI   128
#define TJ   64
#define SPLITS 4
#define NT   (NN / SPLITS / TJ)   // 8
#define ALPHA 0.2f

// dynamic smem layout (bytes) for attn kernel
#define SM_PHI  0          // p hi  [128 rows x 128B]  (single buffer)
#define SM_PLO  16384      // p lo
#define SM_WHHI 32768      // wh hi [2][64 rows x 128B]
#define SM_WHLO 49152      // wh lo [2][...]
#define SM_FJ   65536      // fj    [2][64 floats]
#define SM_TOTAL 66048

// ---- scratch ----
__device__ float    g_Wh[BB * NN * FO];
__device__ float    g_fi[BB * NN];
__device__ float    g_fj[BB * NN];
__device__ unsigned g_WhT_hi[BB * FO * (NN / 2)];   // bf16x2 [b][o][j/2] (n-major)
__device__ unsigned g_WhT_lo[BB * FO * (NN / 2)];
__device__ float    g_part[SPLITS * BB * NN * FO];
__device__ float    g_rsum[SPLITS * BB * NN];

// ---- f32x2 helpers (wh kernel) ----
__device__ __forceinline__ void fma2(unsigned long long& d, unsigned long long a, unsigned long long b) {
    asm("fma.rn.f32x2 %0, %1, %2, %0;" : "+l"(d) : "l"(a), "l"(b));
}
__device__ __forceinline__ unsigned long long pack2(float x, float y) {
    unsigned long long r; asm("mov.b64 %0, {%1, %2};" : "=l"(r) : "f"(x), "f"(y)); return r;
}
__device__ __forceinline__ float2 unpack2(unsigned long long v) {
    float2 r; asm("mov.b64 {%0, %1}, %2;" : "=f"(r.x), "=f"(r.y) : "l"(v)); return r;
}

// ---- cp.async ----
__device__ __forceinline__ void cpasync16(unsigned s, const void* g) {
    asm volatile("cp.async.cg.shared.global [%0], [%1], 16;" :: "r"(s), "l"(g) : "memory");
}
__device__ __forceinline__ void cpasync_commit() { asm volatile("cp.async.commit_group;" ::: "memory"); }
__device__ __forceinline__ void cpasync_wait_all() {
    asm volatile("cp.async.wait_group 0;" ::: "memory");
}

// ---- tensor-core (base ISA: works on plain sm_103 target) ----
__device__ __forceinline__ void ldm_x4(unsigned* d, unsigned saddr) {
    asm volatile("ldmatrix.sync.aligned.m8n8.x4.shared.b16 {%0,%1,%2,%3}, [%4];"
                 : "=r"(d[0]), "=r"(d[1]), "=r"(d[2]), "=r"(d[3]) : "r"(saddr));
}
__device__ __forceinline__ void mma_bf16(float* d, const unsigned* a, unsigned b0, unsigned b1) {
    asm volatile("mma.sync.aligned.m16n8k16.row.col.f32.bf16.bf16.f32 "
                 "{%0,%1,%2,%3}, {%4,%5,%6,%7}, {%8,%9}, {%0,%1,%2,%3};"
                 : "+f"(d[0]), "+f"(d[1]), "+f"(d[2]), "+f"(d[3])
                 : "r"(a[0]), "r"(a[1]), "r"(a[2]), "r"(a[3]), "r"(b0), "r"(b1));
}

__device__ __forceinline__ unsigned pack_bf16x2(float lo_v, float hi_v) {
    unsigned r; asm("cvt.rn.bf16x2.f32 %0, %1, %2;" : "=r"(r) : "f"(hi_v), "f"(lo_v)); return r;
}
// split two fp32 into (hi-pair, lo-pair) bf16x2
__device__ __forceinline__ void split2(float v0, float v1, unsigned& hi, unsigned& lo) {
    unsigned b0 = __float_as_uint(v0), b1 = __float_as_uint(v1);
    hi = (b0 >> 16) | (b1 & 0xFFFF0000u);
    float h0 = __uint_as_float(b0 & 0xFFFF0000u);
    float h1 = __uint_as_float(b1 & 0xFFFF0000u);
    lo = pack_bf16x2(v0 - h0, v1 - h1);
}

// ============================================================
// Kernel 1: Wh = h @ W (+ masked f_i, f_j)
// ============================================================
__global__ __launch_bounds__(256)
void gat_wh_kernel(const float* __restrict__ h, const float* __restrict__ W,
                   const float* __restrict__ a, const float* __restrict__ mask) {
    __shared__ float h_s[32 * FIN];
    __shared__ float W_s[FIN * FO];

    int tid = threadIdx.x;
    size_t base = (size_t)blockIdx.x * 32;
    {
        const float4* hsrc = (const float4*)(h + base * FIN);
        float4* hdst = (float4*)h_s;
        #pragma unroll
        for (int r = 0; r < 4; r++) hdst[r * 256 + tid] = hsrc[r * 256 + tid];
        const float4* wsrc = (const float4*)W;
        float4* wdst = (float4*)W_s;
        #pragma unroll
        for (int r = 0; r < 8; r++) wdst[r * 256 + tid] = wsrc[r * 256 + tid];
    }
    __syncthreads();

    int r = tid >> 4, og = tid & 15;
    unsigned long long acc0 = 0, acc1 = 0, acc2 = 0, acc3 = 0;
    const float* hrowA = h_s + r * FIN;
    const float* hrowB = h_s + (r + 16) * FIN;
    #pragma unroll 4
    for (int k = 0; k < FIN; k += 4) {
        float4 ha = *(const float4*)(hrowA + k);
        float4 hb = *(const float4*)(hrowB + k);
        #pragma unroll
        for (int t = 0; t < 4; t++) {
            float va = (t == 0) ? ha.x : (t == 1) ? ha.y : (t == 2) ? ha.z : ha.w;
            float vb = (t == 0) ? hb.x : (t == 1) ? hb.y : (t == 2) ? hb.z : hb.w;
            ulonglong2 w = *(const ulonglong2*)(W_s + (k + t) * FO + og * 4);
            unsigned long long va2 = pack2(va, va), vb2 = pack2(vb, vb);
            fma2(acc0, va2, w.x); fma2(acc1, va2, w.y);
            fma2(acc2, vb2, w.x); fma2(acc3, vb2, w.y);
        }
    }
    int o = og * 4;
    #pragma unroll
    for (int half = 0; half < 2; half++) {
        float2 p01 = unpack2(half ? acc2 : acc0);
        float2 p23 = unpack2(half ? acc3 : acc1);
        size_t row = base + r + half * 16;
        ((float4*)(g_Wh + row * FO))[og] = make_float4(p01.x, p01.y, p23.x, p23.y);
        float ps = p01.x * a[o]      + p01.y * a[o + 1]      + p23.x * a[o + 2]      + p23.y * a[o + 3];
        float pd = p01.x * a[FO + o] + p01.y * a[FO + o + 1] + p23.x * a[FO + o + 2] + p23.y * a[FO + o + 3];
        #pragma unroll
        for (int off = 8; off >= 1; off >>= 1) {
            ps += __shfl_down_sync(0xffffffffu, ps, off, 16);
            pd += __shfl_down_sync(0xffffffffu, pd, off, 16);
        }
        if (og == 0) {
            bool ok = mask[row] > 0.f;
            g_fi[row] = ok ? ps : -1e30f;
            g_fj[row] = ok ? pd : -1e30f;
        }
    }
}

// ============================================================
// Kernel 1b: WhT split to bf16 hi/lo, n-major: WhT[b][o][j]
// ============================================================
__global__ __launch_bounds__(256)
void gat_wht_kernel() {
    __shared__ float tile[64][68];
    int tid = threadIdx.x;
    int j0 = blockIdx.x * 64;
    int b  = blockIdx.y;
    const float4* src = (const float4*)(g_Wh + (size_t)b * NN * FO + (size_t)j0 * FO);
    #pragma unroll
    for (int k = 0; k < 4; k++) {
        int idx = k * 256 + tid;
        int r = idx >> 4, c4 = idx & 15;
        float4 v = src[idx];
        tile[r][c4 * 4 + 0] = v.x; tile[r][c4 * 4 + 1] = v.y;
        tile[r][c4 * 4 + 2] = v.z; tile[r][c4 * 4 + 3] = v.w;
    }
    __syncthreads();
    int o = tid >> 2, cc = tid & 3;
    unsigned oh[8], ol[8];
    #pragma unroll
    for (int u = 0; u < 8; u++) {
        int j = cc * 16 + u * 2;
        split2(tile[j][o], tile[j + 1][o], oh[u], ol[u]);
    }
    size_t ob = (size_t)b * FO * (NN / 2) + (size_t)o * (NN / 2) + j0 / 2 + cc * 8;
    *(uint4*)(g_WhT_hi + ob)     = make_uint4(oh[0], oh[1], oh[2], oh[3]);
    *(uint4*)(g_WhT_hi + ob + 4) = make_uint4(oh[4], oh[5], oh[6], oh[7]);
    *(uint4*)(g_WhT_lo + ob)     = make_uint4(ol[0], ol[1], ol[2], ol[3]);
    *(uint4*)(g_WhT_lo + ob + 4) = make_uint4(ol[4], ol[5], ol[6], ol[7]);
}

// ============================================================
// Kernel 2: attention via ldmatrix + mma.sync (bf16 split x3).
// 128 threads / 4 warps; warp w: rows 32w..32w+31, N=64, K=64/tile.
// ============================================================
__device__ __forceinline__ void load_wh_tile(unsigned sbase, int buf, const unsigned* hi_g,
                                             const unsigned* lo_g, const float* fj_g,
                                             int jt, int tid) {
    #pragma unroll
    for (int k = 0; k < 4; k++) {
        int idx = tid + k * 128;              // 0..511
        int o = idx >> 3, cc = idx & 7;
        unsigned co = (unsigned)(((cc ^ (o & 7))) * 16);
        cpasync16(sbase + SM_WHHI + buf * 8192 + o * 128 + co,
                  hi_g + (size_t)o * (NN / 2) + jt * 32 + cc * 4);
        cpasync16(sbase + SM_WHLO + buf * 8192 + o * 128 + co,
                  lo_g + (size_t)o * (NN / 2) + jt * 32 + cc * 4);
    }
    if (tid < 16)
        cpasync16(sbase + SM_FJ + buf * 256 + tid * 16, fj_g + jt * TJ + tid * 4);
}

__global__ __launch_bounds__(128)
void gat_attn_hmma(const float* __restrict__ adj,
                   float* __restrict__ part, float* __restrict__ rsum) {
    extern __shared__ char smem[];
    unsigned sbase = (unsigned)__cvta_generic_to_shared(smem);
    const int tid = threadIdx.x;
    const int wid = tid >> 5, lane = tid & 31;
    const int b = blockIdx.y, s = blockIdx.z;
    const int i0 = blockIdx.x * TI;
    const int jbeg = s * (NN / SPLITS);

    const float* adj_r = adj + (size_t)b * NN * NN + (size_t)(i0 + tid) * NN + jbeg;
    const float* fj_g  = g_fj + b * NN + jbeg;
    const float  fiv   = g_fi[b * NN + i0 + tid];
    const unsigned* whhi_g = g_WhT_hi + (size_t)b * FO * (NN / 2) + jbeg / 2;
    const unsigned* whlo_g = g_WhT_lo + (size_t)b * FO * (NN / 2) + jbeg / 2;

    float dacc[2][8][4];
    #pragma unroll
    for (int mb = 0; mb < 2; mb++)
        #pragma unroll
        for (int nb = 0; nb < 8; nb++)
            #pragma unroll
            for (int z = 0; z < 4; z++) dacc[mb][nb][z] = 0.f;
    float rowsum = 0.f;

    // prologue: tile 0 wh+fj
    load_wh_tile(sbase, 0, whhi_g, whlo_g, fj_g, 0, tid);
    cpasync_commit();

    // precompute per-lane ldmatrix row/chunk components
    const int a_roff = ((lane >> 3) & 1) * 8 + (lane & 7);  // + mb base
    const int a_cs   = lane >> 4;                           // 0/1
    const int b_roff = ((lane >> 4) << 3) + (lane & 7);     // + nb2*16
    const int b_cs   = (lane >> 3) & 1;

    for (int t = 0; t < NT; t++) {
        int c = t & 1;

        cpasync_wait_all();
        __syncthreads();   // wh(t)/fj(t) visible; everyone done reading p(t-1)

        // ---- p-stage: thread = i-row, 64 edges, fp32 rowsum, bf16 hi/lo store ----
        {
            const float4* ap = (const float4*)(adj_r + t * TJ);
            const float4* fp = (const float4*)(smem + SM_FJ + c * 256);
            #pragma unroll
            for (int g = 0; g < 8; g++) {
                float4 a0 = ap[2 * g], a1 = ap[2 * g + 1];
                float4 f0 = fp[2 * g], f1 = fp[2 * g + 1];
                float p[8];
                {
                    float xs[8] = { fiv + f0.x, fiv + f0.y, fiv + f0.z, fiv + f0.w,
                                    fiv + f1.x, fiv + f1.y, fiv + f1.z, fiv + f1.w };
                    float av[8] = { a0.x, a0.y, a0.z, a0.w, a1.x, a1.y, a1.z, a1.w };
                    #pragma unroll
                    for (int e = 0; e < 8; e++) {
                        float l = fmaxf(xs[e], ALPHA * xs[e]);
                        p[e] = (av[e] > 0.f) ? __expf(l) : 0.f;
                        rowsum += p[e];
                    }
                }
                unsigned h0, h1, h2, h3, l0, l1, l2, l3;
                split2(p[0], p[1], h0, l0);
                split2(p[2], p[3], h1, l1);
                split2(p[4], p[5], h2, l2);
                split2(p[6], p[7], h3, l3);
                int co = (g ^ (tid & 7)) << 4;
                *(uint4*)(smem + SM_PHI + tid * 128 + co) = make_uint4(h0, h1, h2, h3);
                *(uint4*)(smem + SM_PLO + tid * 128 + co) = make_uint4(l0, l1, l2, l3);
            }
        }
        __syncthreads();   // p(t) visible

        // prefetch wh(t+1)
        if (t + 1 < NT) {
            load_wh_tile(sbase, 1 - c, whhi_g, whlo_g, fj_g, t + 1, tid);
            cpasync_commit();
        }

        // ---- mma stage ----
        unsigned whb_hi = sbase + SM_WHHI + c * 8192;
        unsigned whb_lo = sbase + SM_WHLO + c * 8192;
        #pragma unroll
        for (int kb = 0; kb < 4; kb++) {
            unsigned ah[2][4], al[2][4], bh[4][4], bl[4][4];
            #pragma unroll
            for (int mb = 0; mb < 2; mb++) {
                int r = 32 * wid + 16 * mb + a_roff;
                int cs = 2 * kb + a_cs;
                unsigned off = (unsigned)(r * 128 + ((cs ^ (r & 7)) << 4));
                ldm_x4(ah[mb], sbase + SM_PHI + off);
                ldm_x4(al[mb], sbase + SM_PLO + off);
            }
            #pragma unroll
            for (int nb2 = 0; nb2 < 4; nb2++) {
                int rn = nb2 * 16 + b_roff;
                int cs = 2 * kb + b_cs;
                unsigned off = (unsigned)(rn * 128 + ((cs ^ (rn & 7)) << 4));
                ldm_x4(bh[nb2], whb_hi + off);
                ldm_x4(bl[nb2], whb_lo + off);
            }
            #pragma unroll
            for (int mb = 0; mb < 2; mb++)
                #pragma unroll
                for (int nb2 = 0; nb2 < 4; nb2++) {
                    // even n-block
                    mma_bf16(dacc[mb][2 * nb2],     ah[mb], bh[nb2][0], bh[nb2][1]);
                    mma_bf16(dacc[mb][2 * nb2],     ah[mb], bl[nb2][0], bl[nb2][1]);
                    mma_bf16(dacc[mb][2 * nb2],     al[mb], bh[nb2][0], bh[nb2][1]);
                    // odd n-block
                    mma_bf16(dacc[mb][2 * nb2 + 1], ah[mb], bh[nb2][2], bh[nb2][3]);
                    mma_bf16(dacc[mb][2 * nb2 + 1], ah[mb], bl[nb2][2], bl[nb2][3]);
                    mma_bf16(dacc[mb][2 * nb2 + 1], al[mb], bh[nb2][2], bh[nb2][3]);
                }
        }
    }

    // ---- epilogue: write partials (raw, normalized later) ----
    size_t rowbase = (size_t)s * BB * NN + (size_t)b * NN + i0;
    #pragma unroll
    for (int mb = 0; mb < 2; mb++) {
        int r0 = 32 * wid + 16 * mb + (lane >> 2);
        #pragma unroll
        for (int nb = 0; nb < 8; nb++) {
            int col = 8 * nb + 2 * (lane & 3);
            *(float2*)(part + (rowbase + r0) * FO + col)     = make_float2(dacc[mb][nb][0], dacc[mb][nb][1]);
            *(float2*)(part + (rowbase + r0 + 8) * FO + col) = make_float2(dacc[mb][nb][2], dacc[mb][nb][3]);
        }
    }
    rsum[rowbase + tid] = rowsum;
}

// ============================================================
// Kernel 3: reduce splits, normalize, relu
// ============================================================
__global__ __launch_bounds__(256)
void gat_reduce_kernel(const float* __restrict__ part,
                       const float* __restrict__ rsum,
                       float* __restrict__ out) {
    int t = blockIdx.x * blockDim.x + threadIdx.x;
    int rowi = t >> 4;
    float rs = 0.f;
    #pragma unroll
    for (int s = 0; s < SPLITS; s++) rs += rsum[(size_t)s * BB * NN + rowi];
    float inv = (rs > 0.f) ? (1.f / rs) : 0.f;
    float4 v = make_float4(0.f, 0.f, 0.f, 0.f);
    #pragma unroll
    for (int s = 0; s < SPLITS; s++) {
        float4 pv = ((const float4*)part)[(size_t)s * BB * NN * 16 + t];
        v.x += pv.x; v.y += pv.y; v.z += pv.z; v.w += pv.w;
    }
    float4 o;
    o.x = fmaxf(v.x * inv, 0.f);
    o.y = fmaxf(v.y * inv, 0.f);
    o.z = fmaxf(v.z * inv, 0.f);
    o.w = fmaxf(v.w * inv, 0.f);
    ((float4*)out)[t] = o;
}

// ============================================================
extern "C" void kernel_launch(void* const* d_in, const int* in_sizes, int n_in,
                              void* d_out, int out_size) {
    const float *h = nullptr, *adj = nullptr, *mask = nullptr, *W = nullptr, *a = nullptr;
    for (int i = 0; i < n_in; i++) {
        switch (in_sizes[i]) {
            case BB * NN * FIN:  h    = (const float*)d_in[i]; break;
            case BB * NN * NN:   adj  = (const float*)d_in[i]; break;
            case BB * NN:        mask = (const float*)d_in[i]; break;
            case FIN * FO:       W    = (const float*)d_in[i]; break;
            case 2 * FO:         a    = (const float*)d_in[i]; break;
        }
    }
    float* out = (float*)d_out;
    float* part; cudaGetSymbolAddress((void**)&part, g_part);
    float* rsum; cudaGetSymbolAddress((void**)&rsum, g_rsum);

    static bool attr_set = false;
    if (!attr_set) {
        cudaFuncSetAttribute(gat_attn_hmma, cudaFuncAttributeMaxDynamicSharedMemorySize, SM_TOTAL);
        attr_set = true;
    }

    gat_wh_kernel<<<BB * NN / 32, 256>>>(h, W, a, mask);
    gat_wht_kernel<<<dim3(NN / 64, BB), 256>>>();
    gat_attn_hmma<<<dim3(NN / TI, BB, SPLITS), 128, SM_TOTAL>>>(adj, part, rsum);
    gat_reduce_kernel<<<BB * NN * 16 / 256, 256>>>(part, rsum, out);
}

// round 9
// speedup vs baseline: 4.3845x; 1.0216x over previous
#include <cuda_runtime.h>
#include <cuda_bf16.h>

#define BB   16
#define NN   2048
#define FIN  128
#define FO   64
#define TI   128
#define TJ   64
#define SPLITS 4
#define NT   (NN / SPLITS / TJ)   // 8
#define ALPHA 0.2f

// dynamic smem layout (bytes) for attn kernel
#define SM_PHI  0          // p hi  [128 x 128B]   (single buffer)
#define SM_PLO  16384      // p lo
#define SM_ADJ  32768      // adj tile [128 x 256B] (single buffer, chunk-swizzled)
#define SM_WHHI 65536      // wh hi [2][64 x 128B]
#define SM_WHLO 81920      // wh lo [2][64 x 128B]
#define SM_FJ   98304      // fj    [2][64 floats]
#define SM_TOTAL 98816

// ---- scratch ----
__device__ float    g_Wh[BB * NN * FO];
__device__ float    g_fi[BB * NN];
__device__ float    g_fj[BB * NN];
__device__ unsigned g_WhT_hi[BB * FO * (NN / 2)];   // bf16x2 [b][o][j/2] (n-major)
__device__ unsigned g_WhT_lo[BB * FO * (NN / 2)];
__device__ float    g_part[SPLITS * BB * NN * FO];
__device__ float    g_rsum[SPLITS * BB * NN];

// ---- f32x2 helpers (wh kernel) ----
__device__ __forceinline__ void fma2(unsigned long long& d, unsigned long long a, unsigned long long b) {
    asm("fma.rn.f32x2 %0, %1, %2, %0;" : "+l"(d) : "l"(a), "l"(b));
}
__device__ __forceinline__ unsigned long long pack2(float x, float y) {
    unsigned long long r; asm("mov.b64 %0, {%1, %2};" : "=l"(r) : "f"(x), "f"(y)); return r;
}
__device__ __forceinline__ float2 unpack2(unsigned long long v) {
    float2 r; asm("mov.b64 {%0, %1}, %2;" : "=f"(r.x), "=f"(r.y) : "l"(v)); return r;
}

// ---- cp.async ----
__device__ __forceinline__ void cpasync16(unsigned s, const void* g) {
    asm volatile("cp.async.cg.shared.global [%0], [%1], 16;" :: "r"(s), "l"(g) : "memory");
}
__device__ __forceinline__ void cpasync_commit() { asm volatile("cp.async.commit_group;" ::: "memory"); }
__device__ __forceinline__ void cpasync_wait_all() {
    asm volatile("cp.async.wait_group 0;" ::: "memory");
}

// ---- tensor-core (base ISA) ----
__device__ __forceinline__ void ldm_x4(unsigned* d, unsigned saddr) {
    asm volatile("ldmatrix.sync.aligned.m8n8.x4.shared.b16 {%0,%1,%2,%3}, [%4];"
                 : "=r"(d[0]), "=r"(d[1]), "=r"(d[2]), "=r"(d[3]) : "r"(saddr));
}
__device__ __forceinline__ void mma_bf16(float* d, const unsigned* a, unsigned b0, unsigned b1) {
    asm volatile("mma.sync.aligned.m16n8k16.row.col.f32.bf16.bf16.f32 "
                 "{%0,%1,%2,%3}, {%4,%5,%6,%7}, {%8,%9}, {%0,%1,%2,%3};"
                 : "+f"(d[0]), "+f"(d[1]), "+f"(d[2]), "+f"(d[3])
                 : "r"(a[0]), "r"(a[1]), "r"(a[2]), "r"(a[3]), "r"(b0), "r"(b1));
}

__device__ __forceinline__ unsigned pack_bf16x2(float lo_v, float hi_v) {
    unsigned r; asm("cvt.rn.bf16x2.f32 %0, %1, %2;" : "=r"(r) : "f"(hi_v), "f"(lo_v)); return r;
}
__device__ __forceinline__ void split2(float v0, float v1, unsigned& hi, unsigned& lo) {
    unsigned b0 = __float_as_uint(v0), b1 = __float_as_uint(v1);
    hi = (b0 >> 16) | (b1 & 0xFFFF0000u);
    float h0 = __uint_as_float(b0 & 0xFFFF0000u);
    float h1 = __uint_as_float(b1 & 0xFFFF0000u);
    lo = pack_bf16x2(v0 - h0, v1 - h1);
}

// ============================================================
// Kernel 1: Wh = h @ W (+ masked f_i, f_j)
// ============================================================
__global__ __launch_bounds__(256)
void gat_wh_kernel(const float* __restrict__ h, const float* __restrict__ W,
                   const float* __restrict__ a, const float* __restrict__ mask) {
    __shared__ float h_s[32 * FIN];
    __shared__ float W_s[FIN * FO];

    int tid = threadIdx.x;
    size_t base = (size_t)blockIdx.x * 32;
    {
        const float4* hsrc = (const float4*)(h + base * FIN);
        float4* hdst = (float4*)h_s;
        #pragma unroll
        for (int r = 0; r < 4; r++) hdst[r * 256 + tid] = hsrc[r * 256 + tid];
        const float4* wsrc = (const float4*)W;
        float4* wdst = (float4*)W_s;
        #pragma unroll
        for (int r = 0; r < 8; r++) wdst[r * 256 + tid] = wsrc[r * 256 + tid];
    }
    __syncthreads();

    int r = tid >> 4, og = tid & 15;
    unsigned long long acc0 = 0, acc1 = 0, acc2 = 0, acc3 = 0;
    const float* hrowA = h_s + r * FIN;
    const float* hrowB = h_s + (r + 16) * FIN;
    #pragma unroll 4
    for (int k = 0; k < FIN; k += 4) {
        float4 ha = *(const float4*)(hrowA + k);
        float4 hb = *(const float4*)(hrowB + k);
        #pragma unroll
        for (int t = 0; t < 4; t++) {
            float va = (t == 0) ? ha.x : (t == 1) ? ha.y : (t == 2) ? ha.z : ha.w;
            float vb = (t == 0) ? hb.x : (t == 1) ? hb.y : (t == 2) ? hb.z : hb.w;
            ulonglong2 w = *(const ulonglong2*)(W_s + (k + t) * FO + og * 4);
            unsigned long long va2 = pack2(va, va), vb2 = pack2(vb, vb);
            fma2(acc0, va2, w.x); fma2(acc1, va2, w.y);
            fma2(acc2, vb2, w.x); fma2(acc3, vb2, w.y);
        }
    }
    int o = og * 4;
    #pragma unroll
    for (int half = 0; half < 2; half++) {
        float2 p01 = unpack2(half ? acc2 : acc0);
        float2 p23 = unpack2(half ? acc3 : acc1);
        size_t row = base + r + half * 16;
        ((float4*)(g_Wh + row * FO))[og] = make_float4(p01.x, p01.y, p23.x, p23.y);
        float ps = p01.x * a[o]      + p01.y * a[o + 1]      + p23.x * a[o + 2]      + p23.y * a[o + 3];
        float pd = p01.x * a[FO + o] + p01.y * a[FO + o + 1] + p23.x * a[FO + o + 2] + p23.y * a[FO + o + 3];
        #pragma unroll
        for (int off = 8; off >= 1; off >>= 1) {
            ps += __shfl_down_sync(0xffffffffu, ps, off, 16);
            pd += __shfl_down_sync(0xffffffffu, pd, off, 16);
        }
        if (og == 0) {
            bool ok = mask[row] > 0.f;
            g_fi[row] = ok ? ps : -1e30f;
            g_fj[row] = ok ? pd : -1e30f;
        }
    }
}

// ============================================================
// Kernel 1b: WhT split to bf16 hi/lo, n-major: WhT[b][o][j]
// ============================================================
__global__ __launch_bounds__(256)
void gat_wht_kernel() {
    __shared__ float tile[64][68];
    int tid = threadIdx.x;
    int j0 = blockIdx.x * 64;
    int b  = blockIdx.y;
    const float4* src = (const float4*)(g_Wh + (size_t)b * NN * FO + (size_t)j0 * FO);
    #pragma unroll
    for (int k = 0; k < 4; k++) {
        int idx = k * 256 + tid;
        int r = idx >> 4, c4 = idx & 15;
        float4 v = src[idx];
        tile[r][c4 * 4 + 0] = v.x; tile[r][c4 * 4 + 1] = v.y;
        tile[r][c4 * 4 + 2] = v.z; tile[r][c4 * 4 + 3] = v.w;
    }
    __syncthreads();
    int o = tid >> 2, cc = tid & 3;
    unsigned oh[8], ol[8];
    #pragma unroll
    for (int u = 0; u < 8; u++) {
        int j = cc * 16 + u * 2;
        split2(tile[j][o], tile[j + 1][o], oh[u], ol[u]);
    }
    size_t ob = (size_t)b * FO * (NN / 2) + (size_t)o * (NN / 2) + j0 / 2 + cc * 8;
    *(uint4*)(g_WhT_hi + ob)     = make_uint4(oh[0], oh[1], oh[2], oh[3]);
    *(uint4*)(g_WhT_hi + ob + 4) = make_uint4(oh[4], oh[5], oh[6], oh[7]);
    *(uint4*)(g_WhT_lo + ob)     = make_uint4(ol[0], ol[1], ol[2], ol[3]);
    *(uint4*)(g_WhT_lo + ob + 4) = make_uint4(ol[4], ol[5], ol[6], ol[7]);
}

// ============================================================
// Kernel 2: attention via ldmatrix + mma.sync (bf16 split x3),
// with adj AND wh both in the cp.async pipeline.
// ============================================================
__device__ __forceinline__ void load_wh_tile(unsigned sbase, int buf, const unsigned* hi_g,
                                             const unsigned* lo_g, const float* fj_g,
                                             int jt, int tid) {
    #pragma unroll
    for (int k = 0; k < 4; k++) {
        int idx = tid + k * 128;              // 0..511
        int o = idx >> 3, cc = idx & 7;
        unsigned co = (unsigned)(((cc ^ (o & 7))) * 16);
        cpasync16(sbase + SM_WHHI + buf * 8192 + o * 128 + co,
                  hi_g + (size_t)o * (NN / 2) + jt * 32 + cc * 4);
        cpasync16(sbase + SM_WHLO + buf * 8192 + o * 128 + co,
                  lo_g + (size_t)o * (NN / 2) + jt * 32 + cc * 4);
    }
    if (tid < 16)
        cpasync16(sbase + SM_FJ + buf * 256 + tid * 16, fj_g + jt * TJ + tid * 4);
}

// adj tile: row tid (256B), 16 chunks of 16B, chunk-swizzled by (c ^ (tid&7))
__device__ __forceinline__ void load_adj_tile(unsigned sbase, const float* adj_row, int t, int tid) {
    unsigned dstrow = sbase + SM_ADJ + (unsigned)tid * 256;
    const float* src = adj_row + t * TJ;
    #pragma unroll
    for (int cchunk = 0; cchunk < 16; cchunk++)
        cpasync16(dstrow + ((unsigned)(cchunk ^ (tid & 7)) << 4), src + cchunk * 4);
}

__global__ __launch_bounds__(128)
void gat_attn_hmma(const float* __restrict__ adj,
                   float* __restrict__ part, float* __restrict__ rsum) {
    extern __shared__ char smem[];
    unsigned sbase = (unsigned)__cvta_generic_to_shared(smem);
    const int tid = threadIdx.x;
    const int wid = tid >> 5, lane = tid & 31;
    const int b = blockIdx.y, s = blockIdx.z;
    const int i0 = blockIdx.x * TI;
    const int jbeg = s * (NN / SPLITS);

    const float* adj_r = adj + (size_t)b * NN * NN + (size_t)(i0 + tid) * NN + jbeg;
    const float* fj_g  = g_fj + b * NN + jbeg;
    const float  fiv   = g_fi[b * NN + i0 + tid];
    const unsigned* whhi_g = g_WhT_hi + (size_t)b * FO * (NN / 2) + jbeg / 2;
    const unsigned* whlo_g = g_WhT_lo + (size_t)b * FO * (NN / 2) + jbeg / 2;

    float dacc[2][8][4];
    #pragma unroll
    for (int mb = 0; mb < 2; mb++)
        #pragma unroll
        for (int nb = 0; nb < 8; nb++)
            #pragma unroll
            for (int z = 0; z < 4; z++) dacc[mb][nb][z] = 0.f;
    float rowsum = 0.f;

    // prologue: adj(0) + wh(0) + fj(0)
    load_adj_tile(sbase, adj_r, 0, tid);
    load_wh_tile(sbase, 0, whhi_g, whlo_g, fj_g, 0, tid);
    cpasync_commit();

    const int a_roff = ((lane >> 3) & 1) * 8 + (lane & 7);
    const int a_cs   = lane >> 4;
    const int b_roff = ((lane >> 4) << 3) + (lane & 7);
    const int b_cs   = (lane >> 3) & 1;

    for (int t = 0; t < NT; t++) {
        int c = t & 1;

        cpasync_wait_all();
        __syncthreads();   // adj(t)/wh(t)/fj(t) visible; p(t-1) fully consumed

        // ---- p-stage: read adj from smem, 64 edges/thread, rowsum, bf16 hi/lo ----
        {
            const float4* fp = (const float4*)(smem + SM_FJ + c * 256);
            const char* arow = smem + SM_ADJ + tid * 256;
            int asw = tid & 7;
            #pragma unroll
            for (int g = 0; g < 8; g++) {
                float4 a0 = *(const float4*)(arow + (((2 * g)     ^ asw) << 4));
                float4 a1 = *(const float4*)(arow + (((2 * g + 1) ^ asw) << 4));
                float4 f0 = fp[2 * g], f1 = fp[2 * g + 1];
                float p[8];
                {
                    float xs[8] = { fiv + f0.x, fiv + f0.y, fiv + f0.z, fiv + f0.w,
                                    fiv + f1.x, fiv + f1.y, fiv + f1.z, fiv + f1.w };
                    float av[8] = { a0.x, a0.y, a0.z, a0.w, a1.x, a1.y, a1.z, a1.w };
                    #pragma unroll
                    for (int e = 0; e < 8; e++) {
                        float l = fmaxf(xs[e], ALPHA * xs[e]);
                        p[e] = (av[e] > 0.f) ? __expf(l) : 0.f;
                        rowsum += p[e];
                    }
                }
                unsigned h0, h1, h2, h3, l0, l1, l2, l3;
                split2(p[0], p[1], h0, l0);
                split2(p[2], p[3], h1, l1);
                split2(p[4], p[5], h2, l2);
                split2(p[6], p[7], h3, l3);
                int co = (g ^ asw) << 4;
                *(uint4*)(smem + SM_PHI + tid * 128 + co) = make_uint4(h0, h1, h2, h3);
                *(uint4*)(smem + SM_PLO + tid * 128 + co) = make_uint4(l0, l1, l2, l3);
            }
        }
        __syncthreads();   // p(t) visible; adjbuf consumed

        // ---- prefetch adj(t+1) + wh(t+1): overlaps mma(t) ----
        if (t + 1 < NT) {
            load_adj_tile(sbase, adj_r, t + 1, tid);
            load_wh_tile(sbase, 1 - c, whhi_g, whlo_g, fj_g, t + 1, tid);
            cpasync_commit();
        }

        // ---- mma stage ----
        unsigned whb_hi = sbase + SM_WHHI + c * 8192;
        unsigned whb_lo = sbase + SM_WHLO + c * 8192;
        #pragma unroll
        for (int kb = 0; kb < 4; kb++) {
            unsigned ah[2][4], al[2][4], bh[4][4], bl[4][4];
            #pragma unroll
            for (int mb = 0; mb < 2; mb++) {
                int r = 32 * wid + 16 * mb + a_roff;
                int cs = 2 * kb + a_cs;
                unsigned off = (unsigned)(r * 128 + ((cs ^ (r & 7)) << 4));
                ldm_x4(ah[mb], sbase + SM_PHI + off);
                ldm_x4(al[mb], sbase + SM_PLO + off);
            }
            #pragma unroll
            for (int nb2 = 0; nb2 < 4; nb2++) {
                int rn = nb2 * 16 + b_roff;
                int cs = 2 * kb + b_cs;
                unsigned off = (unsigned)(rn * 128 + ((cs ^ (rn & 7)) << 4));
                ldm_x4(bh[nb2], whb_hi + off);
                ldm_x4(bl[nb2], whb_lo + off);
            }
            #pragma unroll
            for (int mb = 0; mb < 2; mb++)
                #pragma unroll
                for (int nb2 = 0; nb2 < 4; nb2++) {
                    mma_bf16(dacc[mb][2 * nb2],     ah[mb], bh[nb2][0], bh[nb2][1]);
                    mma_bf16(dacc[mb][2 * nb2],     ah[mb], bl[nb2][0], bl[nb2][1]);
                    mma_bf16(dacc[mb][2 * nb2],     al[mb], bh[nb2][0], bh[nb2][1]);
                    mma_bf16(dacc[mb][2 * nb2 + 1], ah[mb], bh[nb2][2], bh[nb2][3]);
                    mma_bf16(dacc[mb][2 * nb2 + 1], ah[mb], bl[nb2][2], bl[nb2][3]);
                    mma_bf16(dacc[mb][2 * nb2 + 1], al[mb], bh[nb2][2], bh[nb2][3]);
                }
        }
    }

    // ---- epilogue ----
    size_t rowbase = (size_t)s * BB * NN + (size_t)b * NN + i0;
    #pragma unroll
    for (int mb = 0; mb < 2; mb++) {
        int r0 = 32 * wid + 16 * mb + (lane >> 2);
        #pragma unroll
        for (int nb = 0; nb < 8; nb++) {
            int col = 8 * nb + 2 * (lane & 3);
            *(float2*)(part + (rowbase + r0) * FO + col)     = make_float2(dacc[mb][nb][0], dacc[mb][nb][1]);
            *(float2*)(part + (rowbase + r0 + 8) * FO + col) = make_float2(dacc[mb][nb][2], dacc[mb][nb][3]);
        }
    }
    rsum[rowbase + tid] = rowsum;
}

// ============================================================
// Kernel 3: reduce splits, normalize, relu
// ============================================================
__global__ __launch_bounds__(256)
void gat_reduce_kernel(const float* __restrict__ part,
                       const float* __restrict__ rsum,
                       float* __restrict__ out) {
    int t = blockIdx.x * blockDim.x + threadIdx.x;
    int rowi = t >> 4;
    float rs = 0.f;
    #pragma unroll
    for (int s = 0; s < SPLITS; s++) rs += rsum[(size_t)s * BB * NN + rowi];
    float inv = (rs > 0.f) ? (1.f / rs) : 0.f;
    float4 v = make_float4(0.f, 0.f, 0.f, 0.f);
    #pragma unroll
    for (int s = 0; s < SPLITS; s++) {
        float4 pv = ((const float4*)part)[(size_t)s * BB * NN * 16 + t];
        v.x += pv.x; v.y += pv.y; v.z += pv.z; v.w += pv.w;
    }
    float4 o;
    o.x = fmaxf(v.x * inv, 0.f);
    o.y = fmaxf(v.y * inv, 0.f);
    o.z = fmaxf(v.z * inv, 0.f);
    o.w = fmaxf(v.w * inv, 0.f);
    ((float4*)out)[t] = o;
}

// ============================================================
extern "C" void kernel_launch(void* const* d_in, const int* in_sizes, int n_in,
                              void* d_out, int out_size) {
    const float *h = nullptr, *adj = nullptr, *mask = nullptr, *W = nullptr, *a = nullptr;
    for (int i = 0; i < n_in; i++) {
        switch (in_sizes[i]) {
            case BB * NN * FIN:  h    = (const float*)d_in[i]; break;
            case BB * NN * NN:   adj  = (const float*)d_in[i]; break;
            case BB * NN:        mask = (const float*)d_in[i]; break;
            case FIN * FO:       W    = (const float*)d_in[i]; break;
            case 2 * FO:         a    = (const float*)d_in[i]; break;
        }
    }
    float* out = (float*)d_out;
    float* part; cudaGetSymbolAddress((void**)&part, g_part);
    float* rsum; cudaGetSymbolAddress((void**)&rsum, g_rsum);

    static bool attr_set = false;
    if (!attr_set) {
        cudaFuncSetAttribute(gat_attn_hmma, cudaFuncAttributeMaxDynamicSharedMemorySize, SM_TOTAL);
        attr_set = true;
    }

    gat_wh_kernel<<<BB * NN / 32, 256>>>(h, W, a, mask);
    gat_wht_kernel<<<dim3(NN / 64, BB), 256>>>();
    gat_attn_hmma<<<dim3(NN / TI, BB, SPLITS), 128, SM_TOTAL>>>(adj, part, rsum);
    gat_reduce_kernel<<<BB * NN * 16 / 256, 256>>>(part, rsum, out);
}